// round 2
// baseline (speedup 1.0000x reference)
#include <cuda_runtime.h>

// GaussianKernel: out[b,l,o] = exp(-gamma * (|x[b,:,l]|^2 + |w[:,o]|^2 - 2 x.w)) + bias[o]
// B=8, K=288, L=16384, O=64. Skinny GEMM [131072, 64, 288] + epilogue.
// Strategy: one thread per (b,l); 64 accumulators as 32 packed f32x2 registers,
// inner product via Blackwell packed fma.rn.f32x2 (FFMA2, 2 fp32 MACs/issue).
// w staged in shared (73.7KB, broadcast LDS.128), x loads fully coalesced.

#define K_DIM 288
#define O_DIM 64
#define L_DIM 16384
#define B_DIM 8
#define TPB   256

// smem: w [288*64] f32 + w2 [64] + bias [64]
#define SMEM_BYTES (K_DIM * O_DIM * 4 + O_DIM * 4 + O_DIM * 4)

__global__ void __launch_bounds__(TPB, 2)
gauss_ffma2_kernel(const float* __restrict__ x,
                   const float* __restrict__ w,
                   const float* __restrict__ bias,
                   const float* __restrict__ gptr,
                   float* __restrict__ out)
{
    extern __shared__ float sm[];
    float* ws  = sm;                        // [K_DIM * O_DIM], wv[k][o] = w_flat[k*64+o]
    float* w2s = sm + K_DIM * O_DIM;        // [O_DIM]
    float* bs  = w2s + O_DIM;               // [O_DIM]

    const int tid = threadIdx.x;

    // Stage w (row-major flatten of [O,32,3,3] reinterpreted as [288][64] — a direct copy).
    for (int i = tid; i < K_DIM * O_DIM; i += TPB) ws[i] = w[i];
    if (tid < O_DIM) bs[tid] = bias[tid];
    __syncthreads();

    // Precompute |w[:,o]|^2 (64 threads, column reads: bank-conflict-free).
    if (tid < O_DIM) {
        float s = 0.f;
        #pragma unroll 8
        for (int k = 0; k < K_DIM; k++) {
            float v = ws[k * O_DIM + tid];
            s = fmaf(v, v, s);
        }
        w2s[tid] = s;
    }
    __syncthreads();

    const int b = blockIdx.x >> 6;                      // 64 CTAs per batch
    const int l = ((blockIdx.x & 63) * TPB) + tid;      // 0..16383
    const float* xp = x + (size_t)b * K_DIM * L_DIM + l;

    // 64 fp32 accumulators as 32 packed f32x2.
    unsigned long long acc[32];
    #pragma unroll
    for (int i = 0; i < 32; i++) acc[i] = 0ULL;
    float x2 = 0.f;

    // Main loop: per k, 1 coalesced LDG (128B/warp), broadcast LDS.128 of w pairs,
    // 32 FFMA2. Unroll 4 for LDG MLP.
    #pragma unroll 4
    for (int k = 0; k < K_DIM; k++) {
        float xv = __ldg(xp + (size_t)k * L_DIM);
        x2 = fmaf(xv, xv, x2);
        unsigned long long xx;
        asm("mov.b64 %0, {%1, %1};" : "=l"(xx) : "f"(xv));
        const ulonglong2* wrow = reinterpret_cast<const ulonglong2*>(ws + k * O_DIM);
        #pragma unroll
        for (int j = 0; j < 16; j++) {
            ulonglong2 wp = wrow[j];
            asm("fma.rn.f32x2 %0, %1, %2, %0;" : "+l"(acc[2 * j])     : "l"(xx), "l"(wp.x));
            asm("fma.rn.f32x2 %0, %1, %2, %0;" : "+l"(acc[2 * j + 1]) : "l"(xx), "l"(wp.y));
        }
    }

    // Epilogue: d2 = x2 + w2[o] - 2*xw; out = exp(-gamma*d2) + bias[o]; float4 stores.
    const float ng = -(*gptr);
    float* op = out + ((size_t)b * L_DIM + l) * O_DIM;
    #pragma unroll
    for (int i = 0; i < 32; i += 2) {
        float a0, a1, a2, a3;
        asm("mov.b64 {%0, %1}, %2;" : "=f"(a0), "=f"(a1) : "l"(acc[i]));
        asm("mov.b64 {%0, %1}, %2;" : "=f"(a2), "=f"(a3) : "l"(acc[i + 1]));
        const int o = 2 * i;
        float4 v;
        v.x = __expf(ng * (x2 + w2s[o + 0] - 2.f * a0)) + bs[o + 0];
        v.y = __expf(ng * (x2 + w2s[o + 1] - 2.f * a1)) + bs[o + 1];
        v.z = __expf(ng * (x2 + w2s[o + 2] - 2.f * a2)) + bs[o + 2];
        v.w = __expf(ng * (x2 + w2s[o + 3] - 2.f * a3)) + bs[o + 3];
        *reinterpret_cast<float4*>(op + o) = v;
    }
}

extern "C" void kernel_launch(void* const* d_in, const int* in_sizes, int n_in,
                              void* d_out, int out_size)
{
    (void)in_sizes; (void)n_in; (void)out_size;
    const float* x     = (const float*)d_in[0];   // [8, 288, 16384]
    const float* w     = (const float*)d_in[1];   // [64, 32, 3, 3] == flat [288][64]
    const float* bias  = (const float*)d_in[2];   // [64]
    const float* gamma = (const float*)d_in[3];   // scalar
    float* out = (float*)d_out;                   // [8, 16384, 64]

    cudaFuncSetAttribute(gauss_ffma2_kernel,
                         cudaFuncAttributeMaxDynamicSharedMemorySize, SMEM_BYTES);

    const int grid = (B_DIM * L_DIM) / TPB;       // 512 CTAs
    gauss_ffma2_kernel<<<grid, TPB, SMEM_BYTES>>>(x, w, bias, gamma, out);
}